// round 16
// baseline (speedup 1.0000x reference)
#include <cuda_runtime.h>
#include <math.h>

#define NN 10000
#define NN2 10048          // padded row count for scratch
#define NF 128
#define NH 64
#define MAXNNZ 2000000
#define ECAP 96            // smem edge cap per row (nnz ~ Binom(10000,.002), max ~45)

// ---------------- scratch (device globals, no allocation) ----------------
__device__ __align__(16) float g_S[NN2 * 128];    // S = adj @ x
__device__ __align__(16) float g_AB[NN2 * 128];   // P2 buffers (gemm12 out), interleaved o|t
__device__ __align__(16) float g_CD[NN2 * 128];   // rep2 buffers (spmm2 out), interleaved o|t
__device__ __align__(16) float g_R[NN2 * NH];     // rep_out

struct __align__(8) Edge { int c; float v; };

__device__ int   g_rowbase[NN];
__device__ int   g_rownnz[NN];
__device__ Edge  g_edge[MAXNNZ];
__device__ int   g_top = 0;
__device__ int   g_ccnt = 0;

__device__ __align__(16) float g_ssrc[NN];
__device__ __align__(16) float g_sdst[NN];
__device__ __align__(16) float g_part[250 * NH];
__device__ __align__(16) float g_Sall[NH];

// ---------------- sparsify + S = adj @ x (gather hidden under the DRAM scan) ----------------
__global__ void __launch_bounds__(256) k_spg(const float* __restrict__ adj,
                                             const float* __restrict__ x) {
    __shared__ int   scol[ECAP];
    __shared__ float sval[ECAP];
    __shared__ int wsum[8];
    __shared__ int sbase_s, snnz_s;
    __shared__ float sS[128];

    int t = threadIdx.x;
    int row = blockIdx.x;
    const float4* rp = (const float4*)(adj + (size_t)row * NN);
    int lane = t & 31, wid = t >> 5;

    float4 v[10];
    #pragma unroll
    for (int i = 0; i < 10; i++) {
        int j = t + 256 * i;
        if (j < NN / 4) v[i] = __ldcs(rp + j);
        else            v[i] = make_float4(0.f, 0.f, 0.f, 0.f);
    }

    int c = 0;
    #pragma unroll
    for (int i = 0; i < 10; i++)
        c += (v[i].x != 0.f) + (v[i].y != 0.f) + (v[i].z != 0.f) + (v[i].w != 0.f);

    int s = c;
    #pragma unroll
    for (int d = 1; d < 32; d <<= 1) {
        int n = __shfl_up_sync(0xffffffffu, s, d);
        if (lane >= d) s += n;
    }
    if (lane == 31) wsum[wid] = s;
    __syncthreads();
    int wbase = 0;
    #pragma unroll
    for (int i = 0; i < 8; i++) wbase += (i < wid) ? wsum[i] : 0;
    int excl = wbase + s - c;
    if (t == 0) {
        int tot = 0;
        #pragma unroll
        for (int i = 0; i < 8; i++) tot += wsum[i];
        int b = atomicAdd(&g_top, tot);
        g_rowbase[row] = b;
        g_rownnz[row]  = tot;
        sbase_s = b;
        snnz_s  = tot;
    }
    __syncthreads();

    int dst = sbase_s + excl;
    int li  = excl;
    #pragma unroll
    for (int i = 0; i < 10; i++) {
        int cb = (t + 256 * i) * 4;
        if (v[i].x != 0.f) { g_edge[dst].c = cb+0; g_edge[dst].v = v[i].x;
                             if (li < ECAP) { scol[li] = cb+0; sval[li] = v[i].x; } dst++; li++; }
        if (v[i].y != 0.f) { g_edge[dst].c = cb+1; g_edge[dst].v = v[i].y;
                             if (li < ECAP) { scol[li] = cb+1; sval[li] = v[i].y; } dst++; li++; }
        if (v[i].z != 0.f) { g_edge[dst].c = cb+2; g_edge[dst].v = v[i].z;
                             if (li < ECAP) { scol[li] = cb+2; sval[li] = v[i].z; } dst++; li++; }
        if (v[i].w != 0.f) { g_edge[dst].c = cb+3; g_edge[dst].v = v[i].w;
                             if (li < ECAP) { scol[li] = cb+3; sval[li] = v[i].w; } dst++; li++; }
    }
    __syncthreads();

    // S[row] = sum_e v_e * x[c_e, :] ; thread t covers feature f, half h of edges
    int nnz = snnz_s;
    int f = t & 127, h = t >> 7;
    float acc = 0.f;
    for (int e = h; e < nnz; e += 2) {
        int cc; float vv;
        if (e < ECAP) { cc = scol[e]; vv = sval[e]; }
        else          { Edge ed = g_edge[sbase_s + e]; cc = ed.c; vv = ed.v; }
        acc += vv * x[(size_t)cc * 128 + f];
    }
    if (h == 0) sS[f] = acc;
    __syncthreads();
    if (h == 1) g_S[(size_t)row * 128 + f] = sS[f] + acc;
}

// ---------------- fused dense: rep1 = relu(S@W0+b0); P2 = rep1@W1 ----------------
// 32-row tiles, 256 threads, both layers without touching DRAM for rep1.
__global__ void __launch_bounds__(256) k_gemm12(
        const float* __restrict__ W0a, const float* __restrict__ W0b,
        const float* __restrict__ b0a, const float* __restrict__ b0b,
        const float* __restrict__ W1a, const float* __restrict__ W1b) {
    __shared__ float Xs[64 * 34];
    __shared__ float Ws[64 * 64];
    __shared__ float R1[64 * 34];    // stage-B X, transposed [k][row]
    __shared__ float Ws2[64 * 64];

    int m = blockIdx.y;
    const float* W0 = m ? W0b : W0a;
    const float* b0 = m ? b0b : b0a;
    const float* W1 = m ? W1b : W1a;
    int tid = threadIdx.x;
    int tx = tid & 15, ty = tid >> 4;
    int r0 = blockIdx.x * 32;
    float acc[2][4] = {};

    // prefetch W1 (independent of stage A)
    {
        const float4* s = (const float4*)W1;
        float4* d = (float4*)Ws2;
        #pragma unroll
        for (int i = 0; i < 4; i++) d[tid + 256 * i] = s[tid + 256 * i];
    }

    // ---- stage A: K=128 over g_S ----
    for (int k0 = 0; k0 < 128; k0 += 64) {
        {
            const float4* s = (const float4*)(W0 + (size_t)k0 * 64);
            float4* d = (float4*)Ws;
            #pragma unroll
            for (int i = 0; i < 4; i++) d[tid + 256 * i] = s[tid + 256 * i];
        }
        #pragma unroll
        for (int i = 0; i < 2; i++) {
            int e = tid + 256 * i;
            int row = e >> 4, c4 = e & 15;
            int rr = r0 + row;
            float4 v = make_float4(0.f, 0.f, 0.f, 0.f);
            if (rr < NN) v = ((const float4*)(g_S + (size_t)rr * 128 + k0))[c4];
            int kk = c4 * 4;
            Xs[(kk + 0) * 34 + row] = v.x;
            Xs[(kk + 1) * 34 + row] = v.y;
            Xs[(kk + 2) * 34 + row] = v.z;
            Xs[(kk + 3) * 34 + row] = v.w;
        }
        __syncthreads();
        #pragma unroll 8
        for (int k = 0; k < 64; k++) {
            float4 wv = *(const float4*)&Ws[k * 64 + tx * 4];
            float2 xv = *(const float2*)&Xs[k * 34 + ty * 2];
            acc[0][0] += xv.x * wv.x; acc[0][1] += xv.x * wv.y;
            acc[0][2] += xv.x * wv.z; acc[0][3] += xv.x * wv.w;
            acc[1][0] += xv.y * wv.x; acc[1][1] += xv.y * wv.y;
            acc[1][2] += xv.y * wv.z; acc[1][3] += xv.y * wv.w;
        }
        __syncthreads();
    }

    // bias + relu, store rep1 transposed into R1
    {
        float4 bv = ((const float4*)b0)[tx];
        #pragma unroll
        for (int i = 0; i < 2; i++) {
            int row = ty * 2 + i;
            R1[(tx * 4 + 0) * 34 + row] = fmaxf(acc[i][0] + bv.x, 0.f);
            R1[(tx * 4 + 1) * 34 + row] = fmaxf(acc[i][1] + bv.y, 0.f);
            R1[(tx * 4 + 2) * 34 + row] = fmaxf(acc[i][2] + bv.z, 0.f);
            R1[(tx * 4 + 3) * 34 + row] = fmaxf(acc[i][3] + bv.w, 0.f);
        }
    }
    __syncthreads();

    // ---- stage B: K=64 over rep1 (smem) ----
    float acc2[2][4] = {};
    #pragma unroll 8
    for (int k = 0; k < 64; k++) {
        float4 wv = *(const float4*)&Ws2[k * 64 + tx * 4];
        float2 xv = *(const float2*)&R1[k * 34 + ty * 2];
        acc2[0][0] += xv.x * wv.x; acc2[0][1] += xv.x * wv.y;
        acc2[0][2] += xv.x * wv.z; acc2[0][3] += xv.x * wv.w;
        acc2[1][0] += xv.y * wv.x; acc2[1][1] += xv.y * wv.y;
        acc2[1][2] += xv.y * wv.z; acc2[1][3] += xv.y * wv.w;
    }
    #pragma unroll
    for (int i = 0; i < 2; i++) {
        int rr = r0 + ty * 2 + i;
        if (rr >= NN) continue;
        float4 o = make_float4(acc2[i][0], acc2[i][1], acc2[i][2], acc2[i][3]);
        *(float4*)(g_AB + (size_t)rr * 128 + m * 64 + tx * 4) = o;
    }
}

// ---------------- fused SpMM2 (+bias+relu) + scores epilogue (R10 form) ----------------
__global__ void k_spmm(const float* __restrict__ b0, const float* __restrict__ b1,
                       const float* __restrict__ a) {
    int row = blockIdx.x;
    int tid = threadIdx.x;          // 64
    int w = tid >> 5, l = tid & 31;
    int base = g_rowbase[row], nnz = g_rownnz[row];
    const float4* __restrict__ AB4 = (const float4*)g_AB;

    __shared__ Edge se[64];
    __shared__ __align__(16) float sbias[128];
    __shared__ float4 red[32];
    __shared__ __align__(16) float srep[128];
    __shared__ float xr[2], xd[2];

    sbias[tid]      = b0[tid];
    sbias[tid + 64] = b1[tid];

    float4 acc[4];
    #pragma unroll
    for (int u = 0; u < 4; u++) acc[u] = make_float4(0.f, 0.f, 0.f, 0.f);

    for (int c0 = 0; c0 < nnz; c0 += 64) {
        int n = min(64, nnz - c0);
        if (tid < n) se[tid] = g_edge[base + c0 + tid];
        __syncthreads();
        int e = w;
        for (; e + 6 < n; e += 8) {
            #pragma unroll
            for (int u = 0; u < 4; u++) {
                Edge ed = se[e + 2 * u];
                float4 p = AB4[(size_t)ed.c * 32 + l];
                acc[u].x += ed.v * p.x; acc[u].y += ed.v * p.y;
                acc[u].z += ed.v * p.z; acc[u].w += ed.v * p.w;
            }
        }
        for (; e < n; e += 2) {
            Edge ed = se[e];
            float4 p = AB4[(size_t)ed.c * 32 + l];
            acc[0].x += ed.v * p.x; acc[0].y += ed.v * p.y;
            acc[0].z += ed.v * p.z; acc[0].w += ed.v * p.w;
        }
        __syncthreads();
    }
    float4 sum;
    sum.x = acc[0].x + acc[1].x + acc[2].x + acc[3].x;
    sum.y = acc[0].y + acc[1].y + acc[2].y + acc[3].y;
    sum.z = acc[0].z + acc[1].z + acc[2].z + acc[3].z;
    sum.w = acc[0].w + acc[1].w + acc[2].w + acc[3].w;

    if (w == 1) red[l] = sum;
    __syncthreads();
    if (w == 0) {
        float4 o = red[l];
        float4 bv = *(const float4*)&sbias[l * 4];
        sum.x = fmaxf(sum.x + o.x + bv.x, 0.f);
        sum.y = fmaxf(sum.y + o.y + bv.y, 0.f);
        sum.z = fmaxf(sum.z + o.z + bv.z, 0.f);
        sum.w = fmaxf(sum.w + o.w + bv.w, 0.f);
        ((float4*)g_CD)[(size_t)row * 32 + l] = sum;
        *(float4*)&srep[l * 4] = sum;
    }
    __syncthreads();
    float rs = srep[tid] * a[tid]       + srep[64 + tid] * a[64 + tid];
    float rd = srep[tid] * a[128 + tid] + srep[64 + tid] * a[192 + tid];
    #pragma unroll
    for (int o = 16; o; o >>= 1) {
        rs += __shfl_xor_sync(0xffffffffu, rs, o);
        rd += __shfl_xor_sync(0xffffffffu, rd, o);
    }
    if (l == 0) { xr[w] = rs; xd[w] = rd; }
    __syncthreads();
    if (tid == 0) { g_ssrc[row] = xr[0] + xr[1]; g_sdst[row] = xd[0] + xd[1]; }
}

// ---------------- colsum (blocks 0..249) + treatment head (blocks 250..406) ----------------
__global__ void __launch_bounds__(256) k_ct(
        const float* __restrict__ Wpp,  const float* __restrict__ bpp,
        const float* __restrict__ Wpp2, const float* __restrict__ bpp2,
        float* __restrict__ dout) {
    __shared__ float U[64 * 65];
    __shared__ float V[64 * 65];
    __shared__ float Ws[64 * 64];
    int tid = threadIdx.x;

    if (blockIdx.x < 250) {
        // ---- colsum role ----
        int b = blockIdx.x;
        int h = tid & 63, qd = tid >> 6;
        int r0 = b * 40 + qd * 10;
        float acc = 0.f;
        #pragma unroll 5
        for (int r = r0; r < r0 + 10; r++) acc += g_CD[(size_t)r * 128 + 64 + h];
        __shared__ float sred[256];
        sred[qd * 64 + h] = acc;
        __syncthreads();
        if (qd == 0) g_part[b * 64 + h] = sred[h] + sred[64 + h] + sred[128 + h] + sred[192 + h];
        __threadfence();
        __syncthreads();
        __shared__ int last;
        if (tid == 0) last = atomicAdd(&g_ccnt, 1);
        __syncthreads();
        if (last == 249) {
            __threadfence();
            if (qd == 0) {
                float s = 0.f;
                for (int i = 0; i < 250; i++) s += g_part[i * 64 + h];  // fixed order
                g_Sall[h] = s;
            }
            if (tid == 0) g_ccnt = 0;
        }
        return;
    }

    // ---- treatment head role ----
    int tx = tid & 15, ty = tid >> 4;
    int r0 = (blockIdx.x - 250) * 64;
    {   // load rep_t tile
        #pragma unroll
        for (int i = 0; i < 4; i++) {
            int e = tid + 256 * i;
            int row = e >> 4, c4 = e & 15;
            float4 v = ((const float4*)(g_CD + 64 + (size_t)(r0 + row) * 128))[c4];
            U[row * 65 + c4 * 4 + 0] = v.x;
            U[row * 65 + c4 * 4 + 1] = v.y;
            U[row * 65 + c4 * 4 + 2] = v.z;
            U[row * 65 + c4 * 4 + 3] = v.w;
        }
        const float4* s = (const float4*)Wpp;
        float4* d = (float4*)Ws;
        #pragma unroll
        for (int i = 0; i < 4; i++) d[tid + 256 * i] = s[tid + 256 * i];
    }
    __syncthreads();
    {
        float acc[4][4] = {};
        #pragma unroll 4
        for (int k = 0; k < 64; k++) {
            float4 wv = *(const float4*)&Ws[k * 64 + tx * 4];
            float xv[4];
            #pragma unroll
            for (int i = 0; i < 4; i++) xv[i] = U[(ty * 4 + i) * 65 + k];
            #pragma unroll
            for (int i = 0; i < 4; i++) {
                acc[i][0] += xv[i] * wv.x; acc[i][1] += xv[i] * wv.y;
                acc[i][2] += xv[i] * wv.z; acc[i][3] += xv[i] * wv.w;
            }
        }
        #pragma unroll
        for (int i = 0; i < 4; i++)
            #pragma unroll
            for (int j = 0; j < 4; j++)
                V[(ty * 4 + i) * 65 + tx * 4 + j] = acc[i][j] + bpp[tx * 4 + j];
    }
    __syncthreads();
    if (tid < 64) {
        int row = r0 + tid;
        if (row < NN) {
            float z0 = 0.f, z1 = 0.f;
            #pragma unroll 4
            for (int k = 0; k < 64; k++) {
                float e = V[tid * 65 + k];
                z0 += e * Wpp2[k * 2];
                z1 += e * Wpp2[k * 2 + 1];
            }
            dout[650000 + (size_t)row * 2 + 0] = 1.f / (1.f + __expf(-(z0 + bpp2[0])));
            dout[650000 + (size_t)row * 2 + 1] = 1.f / (1.f + __expf(-(z1 + bpp2[1])));
        }
    }
    if (blockIdx.x == 250 && tid == 0) g_top = 0;   // re-arm edge pool for next replay
}

// ---------------- attention: half-warp float4 gather (R10) ----------------
__global__ void k_att(float* __restrict__ dout) {
    int row = blockIdx.x * 2 + threadIdx.y;
    int l = threadIdx.x;
    int half = l >> 4, q = l & 15;
    int base = g_rowbase[row], nnz = g_rownnz[row];
    float si = g_ssrc[row];

    float lm = -1e30f;
    for (int e = l; e < nnz; e += 32)
        lm = fmaxf(lm, g_sdst[g_edge[base + e].c]);
    #pragma unroll
    for (int o = 16; o; o >>= 1)
        lm = fmaxf(lm, __shfl_xor_sync(0xffffffffu, lm, o));
    float mm = fmaxf(si + lm, 0.f);

    const float4* __restrict__ CD4 = (const float4*)g_CD;
    float4 aW0 = {0.f,0.f,0.f,0.f}, aW1 = aW0, aR0 = aW0, aR1 = aW0;
    float sw = 0.f;
    int e = half;
    for (; e + 2 < nnz; e += 4) {
        int c0 = g_edge[base + e].c;
        int c1 = g_edge[base + e + 2].c;
        float w0 = __expf(si + g_sdst[c0] - mm);
        float w1 = __expf(si + g_sdst[c1] - mm);
        float4 p0 = CD4[(size_t)c0 * 32 + 16 + q];
        float4 p1 = CD4[(size_t)c1 * 32 + 16 + q];
        aW0.x += w0 * p0.x; aW0.y += w0 * p0.y; aW0.z += w0 * p0.z; aW0.w += w0 * p0.w;
        aW1.x += w1 * p1.x; aW1.y += w1 * p1.y; aW1.z += w1 * p1.z; aW1.w += w1 * p1.w;
        aR0.x += p0.x; aR0.y += p0.y; aR0.z += p0.z; aR0.w += p0.w;
        aR1.x += p1.x; aR1.y += p1.y; aR1.z += p1.z; aR1.w += p1.w;
        sw += w0 + w1;
    }
    for (; e < nnz; e += 2) {
        int cc = g_edge[base + e].c;
        float wt = __expf(si + g_sdst[cc] - mm);
        float4 p = CD4[(size_t)cc * 32 + 16 + q];
        aW0.x += wt * p.x; aW0.y += wt * p.y; aW0.z += wt * p.z; aW0.w += wt * p.w;
        aR0.x += p.x; aR0.y += p.y; aR0.z += p.z; aR0.w += p.w;
        sw += wt;
    }
    float4 aW, aR;
    aW.x = aW0.x + aW1.x; aW.y = aW0.y + aW1.y; aW.z = aW0.z + aW1.z; aW.w = aW0.w + aW1.w;
    aR.x = aR0.x + aR1.x; aR.y = aR0.y + aR1.y; aR.z = aR0.z + aR1.z; aR.w = aR0.w + aR1.w;

    sw   += __shfl_xor_sync(0xffffffffu, sw, 16);
    aW.x += __shfl_xor_sync(0xffffffffu, aW.x, 16);
    aW.y += __shfl_xor_sync(0xffffffffu, aW.y, 16);
    aW.z += __shfl_xor_sync(0xffffffffu, aW.z, 16);
    aW.w += __shfl_xor_sync(0xffffffffu, aW.w, 16);
    aR.x += __shfl_xor_sync(0xffffffffu, aR.x, 16);
    aR.y += __shfl_xor_sync(0xffffffffu, aR.y, 16);
    aR.z += __shfl_xor_sync(0xffffffffu, aR.z, 16);
    aR.w += __shfl_xor_sync(0xffffffffu, aR.w, 16);

    float em = __expf(-mm);
    float denom = (float)(NN - nnz) * em + sw;
    if (half == 0) {
        float4 S = ((const float4*)g_Sall)[q];
        float4 C = CD4[(size_t)row * 32 + q];
        float4 v;
        v.x = (em * (S.x - aR.x) + aW.x) / denom + C.x;
        v.y = (em * (S.y - aR.y) + aW.y) / denom + C.y;
        v.z = (em * (S.z - aR.z) + aW.z) / denom + C.z;
        v.w = (em * (S.w - aR.w) + aW.w) / denom + C.w;
        ((float4*)(dout + 10000))[(size_t)row * 16 + q] = v;
        ((float4*)g_R)[(size_t)row * 16 + q] = v;
    }
}

// ---------------- heads: 2-way block split (outcome paths 0/1) ----------------
__global__ void __launch_bounds__(256) k_heads(
        const int* __restrict__ t,
        const float* __restrict__ W000, const float* __restrict__ b000,
        const float* __restrict__ W001, const float* __restrict__ b001,
        const float* __restrict__ W100, const float* __restrict__ b100,
        const float* __restrict__ W101, const float* __restrict__ b101,
        const float* __restrict__ Wo0,  const float* __restrict__ bo0,
        const float* __restrict__ Wo1,  const float* __restrict__ bo1,
        float* __restrict__ dout) {
    __shared__ float U[64 * 65];
    __shared__ float V[64 * 65];
    __shared__ float Ws[64 * 64];
    __shared__ float sWv[64];

    int tid = threadIdx.x;
    int tx = tid & 15, ty = tid >> 4;
    int r0 = blockIdx.x * 64;
    int p = blockIdx.y;

    auto loadW = [&](const float* W) {
        const float4* s = (const float4*)W;
        float4* d = (float4*)Ws;
        #pragma unroll
        for (int i = 0; i < 4; i++) d[tid + 256 * i] = s[tid + 256 * i];
    };
    auto stage = [&](const float* in, float* outp, const float* b) {
        float acc[4][4] = {};
        #pragma unroll 4
        for (int k = 0; k < 64; k++) {
            float4 wv = *(const float4*)&Ws[k * 64 + tx * 4];
            float xv[4];
            #pragma unroll
            for (int i = 0; i < 4; i++) xv[i] = in[(ty * 4 + i) * 65 + k];
            #pragma unroll
            for (int i = 0; i < 4; i++) {
                acc[i][0] += xv[i] * wv.x; acc[i][1] += xv[i] * wv.y;
                acc[i][2] += xv[i] * wv.z; acc[i][3] += xv[i] * wv.w;
            }
        }
        #pragma unroll
        for (int i = 0; i < 4; i++)
            #pragma unroll
            for (int j = 0; j < 4; j++)
                outp[(ty * 4 + i) * 65 + tx * 4 + j] =
                    fmaxf(acc[i][j] + b[tx * 4 + j], 0.f);
    };

    const float* Wa = p ? W100 : W000;
    const float* ba = p ? b100 : b000;
    const float* Wb = p ? W101 : W001;
    const float* bb = p ? b101 : b001;
    const float* Wo = p ? Wo1  : Wo0;
    float bo = p ? bo1[0] : bo0[0];

    {   // load rep_out tile
        #pragma unroll
        for (int i = 0; i < 4; i++) {
            int e = tid + 256 * i;
            int row = e >> 4, c4 = e & 15;
            float4 v = ((const float4*)(g_R + (size_t)(r0 + row) * 64))[c4];
            U[row * 65 + c4 * 4 + 0] = v.x;
            U[row * 65 + c4 * 4 + 1] = v.y;
            U[row * 65 + c4 * 4 + 2] = v.z;
            U[row * 65 + c4 * 4 + 3] = v.w;
        }
    }
    loadW(Wa);
    if (tid < 64) sWv[tid] = Wo[tid];
    __syncthreads();
    stage(U, V, ba);
    __syncthreads();
    loadW(Wb);
    __syncthreads();
    stage(V, U, bb);
    __syncthreads();

    if (tid < 64) {
        int row = r0 + tid;
        if (row < NN && (t[row] > 0) == (p == 1)) {
            float acc = 0.f;
            #pragma unroll 4
            for (int k = 0; k < 64; k++) acc += U[tid * 65 + k] * sWv[k];
            dout[row] = acc + bo;
        }
    }
}

// ---------------- launch ----------------
extern "C" void kernel_launch(void* const* d_in, const int* in_sizes, int n_in,
                              void* d_out, int out_size) {
    const float* x    = (const float*)d_in[0];
    const float* adj  = (const float*)d_in[1];
    const int*   t    = (const int*)d_in[2];
    const float* Wg0  = (const float*)d_in[3];
    const float* bg0  = (const float*)d_in[4];
    const float* Wg1  = (const float*)d_in[5];
    const float* bg1  = (const float*)d_in[6];
    const float* Wt0  = (const float*)d_in[7];
    const float* bt0  = (const float*)d_in[8];
    const float* Wt1  = (const float*)d_in[9];
    const float* bt1  = (const float*)d_in[10];
    const float* W000 = (const float*)d_in[11];
    const float* b000 = (const float*)d_in[12];
    const float* W001 = (const float*)d_in[13];
    const float* b001 = (const float*)d_in[14];
    const float* W100 = (const float*)d_in[15];
    const float* b100 = (const float*)d_in[16];
    const float* W101 = (const float*)d_in[17];
    const float* b101 = (const float*)d_in[18];
    const float* Wo0  = (const float*)d_in[19];
    const float* bo0  = (const float*)d_in[20];
    const float* Wo1  = (const float*)d_in[21];
    const float* bo1  = (const float*)d_in[22];
    const float* Wpp  = (const float*)d_in[23];
    const float* bpp  = (const float*)d_in[24];
    const float* Wpp2 = (const float*)d_in[25];
    const float* bpp2 = (const float*)d_in[26];
    const float* a    = (const float*)d_in[27];
    float* out = (float*)d_out;

    // sparsify + S = adj @ x (gather hidden under DRAM scan)
    k_spg<<<NN, 256>>>(adj, x);

    // fused dense layers: rep1 = relu(S@W0+b0); P2 = rep1@W1 (rep1 stays in smem)
    k_gemm12<<<dim3(313, 2), 256>>>(Wg0, Wt0, bg0, bt0, Wg1, Wt1);

    // rep2 = relu(adj@P2 + b1) + attention scores
    k_spmm<<<NN, 64>>>(bg1, bt1, a);

    // colsum (250 blocks) + treatment head (157 blocks), one launch
    k_ct<<<407, 256>>>(Wpp, bpp, Wpp2, bpp2, out);

    k_att<<<5000, dim3(32, 2)>>>(out);

    k_heads<<<dim3(157, 2), 256>>>(t, W000, b000, W001, b001, W100, b100, W101, b101,
                                   Wo0, bo0, Wo1, bo1, out);
}